// round 1
// baseline (speedup 1.0000x reference)
#include <cuda_runtime.h>
#include <cstdint>

// 4-table EmbeddingBagCollection: B bags, D=64, out [B, 4*64] fp32.
// Pooling: tables 0,1 = sum; tables 2,3 = mean (empty bag -> 0).
// One warp per (bag, table). Lane l owns output columns {2l, 2l+1} (float2).
// Row gather: warp reads emb[idx]*64..+63 as 32 x float2 -> two full 128B lines.

#define WARPS_PER_BLOCK 8
#define THREADS_PER_BLOCK (WARPS_PER_BLOCK * 32)

__global__ __launch_bounds__(THREADS_PER_BLOCK)
void ebc_kernel(const float* __restrict__ e0, const float* __restrict__ e1,
                const float* __restrict__ e2, const float* __restrict__ e3,
                const int* __restrict__ v0, const int* __restrict__ v1,
                const int* __restrict__ v2, const int* __restrict__ v3,
                const int* __restrict__ offsets,
                float* __restrict__ out, int B)
{
    int warp_id = (blockIdx.x * blockDim.x + threadIdx.x) >> 5;
    int lane = threadIdx.x & 31;
    int nwarps_needed = B * 4;
    if (warp_id >= nwarps_needed) return;

    int t = warp_id & 3;        // table
    int b = warp_id >> 2;       // bag

    const float* emb;
    const int* vals;
    switch (t) {
        case 0: emb = e0; vals = v0; break;
        case 1: emb = e1; vals = v1; break;
        case 2: emb = e2; vals = v2; break;
        default: emb = e3; vals = v3; break;
    }

    int start = __ldg(&offsets[b]);
    int end   = __ldg(&offsets[b + 1]);

    const float2* E = reinterpret_cast<const float2*>(emb);

    float2 acc = make_float2(0.f, 0.f);

    int i = start;
    // 4-wide unroll: 4 independent row loads in flight per lane.
    for (; i + 4 <= end; i += 4) {
        int i0 = __ldg(&vals[i + 0]);
        int i1 = __ldg(&vals[i + 1]);
        int i2 = __ldg(&vals[i + 2]);
        int i3 = __ldg(&vals[i + 3]);
        float2 a = __ldg(&E[(size_t)i0 * 32 + lane]);
        float2 c = __ldg(&E[(size_t)i1 * 32 + lane]);
        float2 d = __ldg(&E[(size_t)i2 * 32 + lane]);
        float2 f = __ldg(&E[(size_t)i3 * 32 + lane]);
        acc.x += a.x + c.x + d.x + f.x;
        acc.y += a.y + c.y + d.y + f.y;
    }
    for (; i < end; ++i) {
        int idx = __ldg(&vals[i]);
        float2 a = __ldg(&E[(size_t)idx * 32 + lane]);
        acc.x += a.x;
        acc.y += a.y;
    }

    if (t >= 2) {  // mean pooling
        int len = end - start;
        if (len > 0) {
            float inv = 1.0f / (float)len;
            acc.x *= inv;
            acc.y *= inv;
        } else {
            acc.x = 0.f;
            acc.y = 0.f;
        }
    }

    // out row b, columns [t*64 + 2*lane, +1]
    float2* orow = reinterpret_cast<float2*>(out + (size_t)b * 256 + t * 64);
    orow[lane] = acc;
}

extern "C" void kernel_launch(void* const* d_in, const int* in_sizes, int n_in,
                              void* d_out, int out_size)
{
    // Resolve inputs by element count (robust to metadata ordering):
    //   emb tables: 64,000,000 elems; values: ~204,800; offsets: B+1 (~4097)
    const float* embs[4] = {nullptr, nullptr, nullptr, nullptr};
    const int*   vals[4] = {nullptr, nullptr, nullptr, nullptr};
    const int*   offsets = nullptr;
    int ne = 0, nv = 0;
    for (int i = 0; i < n_in; ++i) {
        if (in_sizes[i] > 10000000) {
            if (ne < 4) embs[ne++] = (const float*)d_in[i];
        } else if (in_sizes[i] > 100000) {
            if (nv < 4) vals[nv++] = (const int*)d_in[i];
        } else {
            offsets = (const int*)d_in[i];
        }
    }

    int B = out_size / 256;  // out is [B, 4*64]
    int nwarps = B * 4;
    int blocks = (nwarps + WARPS_PER_BLOCK - 1) / WARPS_PER_BLOCK;

    ebc_kernel<<<blocks, THREADS_PER_BLOCK>>>(
        embs[0], embs[1], embs[2], embs[3],
        vals[0], vals[1], vals[2], vals[3],
        offsets, (float*)d_out, B);
}

// round 2
// speedup vs baseline: 1.7217x; 1.7217x over previous
#include <cuda_runtime.h>
#include <cstdint>

// 4-table EmbeddingBagCollection: B bags, D=64, out [B, 4*64] fp32.
// Pooling: tables 0,1 = sum; tables 2,3 = mean (empty bag -> 0).
//
// R2: one BLOCK (8 warps) per (bag, table). Warp w handles values
// start+w, start+w+8, ... (stride 8) -> worst-case warp quantum = len/8.
// Deterministic fixed-order smem reduce by warp 0. 16384 blocks ~= 14 waves
// gives the scheduler slack to smooth the bag-length imbalance.

#define NWARPS 8
#define NTHREADS (NWARPS * 32)

__global__ __launch_bounds__(NTHREADS)
void ebc_kernel(const float* __restrict__ e0, const float* __restrict__ e1,
                const float* __restrict__ e2, const float* __restrict__ e3,
                const int* __restrict__ v0, const int* __restrict__ v1,
                const int* __restrict__ v2, const int* __restrict__ v3,
                const int* __restrict__ offsets,
                float* __restrict__ out)
{
    int blk  = blockIdx.x;
    int t    = blk & 3;          // table
    int b    = blk >> 2;         // bag
    int warp = threadIdx.x >> 5;
    int lane = threadIdx.x & 31;

    const float* emb;
    const int* vals;
    switch (t) {
        case 0: emb = e0; vals = v0; break;
        case 1: emb = e1; vals = v1; break;
        case 2: emb = e2; vals = v2; break;
        default: emb = e3; vals = v3; break;
    }

    int start = __ldg(&offsets[b]);
    int end   = __ldg(&offsets[b + 1]);

    const float2* E = reinterpret_cast<const float2*>(emb);

    float2 acc = make_float2(0.f, 0.f);

    // Warp-strided over the bag: i = start+warp, +8, +16, ...
    int i = start + warp;
    // 4-deep pipelined unroll (stride 32) for MLP.
    for (; i + 24 < end; i += 32) {
        int i0 = __ldg(&vals[i +  0]);
        int i1 = __ldg(&vals[i +  8]);
        int i2 = __ldg(&vals[i + 16]);
        int i3 = __ldg(&vals[i + 24]);
        float2 a = __ldg(&E[(size_t)i0 * 32 + lane]);
        float2 c = __ldg(&E[(size_t)i1 * 32 + lane]);
        float2 d = __ldg(&E[(size_t)i2 * 32 + lane]);
        float2 f = __ldg(&E[(size_t)i3 * 32 + lane]);
        acc.x += a.x + c.x + d.x + f.x;
        acc.y += a.y + c.y + d.y + f.y;
    }
    for (; i < end; i += 8) {
        int idx = __ldg(&vals[i]);
        float2 a = __ldg(&E[(size_t)idx * 32 + lane]);
        acc.x += a.x;
        acc.y += a.y;
    }

    __shared__ float2 red[NWARPS][32];
    red[warp][lane] = acc;
    __syncthreads();

    if (warp == 0) {
        // Fixed-order reduction: deterministic.
        float2 s = red[0][lane];
        #pragma unroll
        for (int w = 1; w < NWARPS; ++w) {
            s.x += red[w][lane].x;
            s.y += red[w][lane].y;
        }

        if (t >= 2) {  // mean pooling
            int len = end - start;
            if (len > 0) {
                float inv = 1.0f / (float)len;
                s.x *= inv; s.y *= inv;
            } else {
                s.x = 0.f; s.y = 0.f;
            }
        }

        float2* orow = reinterpret_cast<float2*>(out + (size_t)b * 256 + t * 64);
        orow[lane] = s;
    }
}

extern "C" void kernel_launch(void* const* d_in, const int* in_sizes, int n_in,
                              void* d_out, int out_size)
{
    // Resolve inputs by element count (robust to metadata ordering):
    //   emb tables: 64,000,000 elems; values: ~204,800; offsets: B+1 (~4097)
    const float* embs[4] = {nullptr, nullptr, nullptr, nullptr};
    const int*   vals[4] = {nullptr, nullptr, nullptr, nullptr};
    const int*   offsets = nullptr;
    int ne = 0, nv = 0;
    for (int i = 0; i < n_in; ++i) {
        if (in_sizes[i] > 10000000) {
            if (ne < 4) embs[ne++] = (const float*)d_in[i];
        } else if (in_sizes[i] > 100000) {
            if (nv < 4) vals[nv++] = (const int*)d_in[i];
        } else {
            offsets = (const int*)d_in[i];
        }
    }

    int B = out_size / 256;  // out is [B, 4*64]
    int blocks = B * 4;      // one block per (bag, table)

    ebc_kernel<<<blocks, NTHREADS>>>(
        embs[0], embs[1], embs[2], embs[3],
        vals[0], vals[1], vals[2], vals[3],
        offsets, (float*)d_out);
}

// round 3
// speedup vs baseline: 1.7701x; 1.0281x over previous
#include <cuda_runtime.h>
#include <cstdint>

// 4-table EmbeddingBagCollection: B bags, D=64, out [B, 4*64] fp32.
// Pooling: tables 0,1 = sum; tables 2,3 = mean (empty bag -> 0).
//
// R3: flat decomposition. Each warp owns a 32-value chunk of one table's
// jagged value array (uniform work, independent of bag lengths). 8-deep
// row prefetch gives MLP=8 per warp. Bag boundaries inside the chunk are
// found by walking offsets (warp-uniform, L1-cached); per-bag partial sums
// are flushed with atomicAdd (spread addresses -> RED at L2).
// Pipeline: memset(out,0) -> gather(+atomics) -> mean divide.

#define CHUNK 32
#define PF 8              // prefetch depth (rows in flight per warp)
#define NTHREADS 256

__global__ __launch_bounds__(NTHREADS)
void ebc_gather(const float* __restrict__ e0, const float* __restrict__ e1,
                const float* __restrict__ e2, const float* __restrict__ e3,
                const int* __restrict__ v0, const int* __restrict__ v1,
                const int* __restrict__ v2, const int* __restrict__ v3,
                const int* __restrict__ offsets,
                float* __restrict__ out, int B,
                int n0, int n1, int n2, int n3, int cpt)
{
    int gw   = (blockIdx.x * blockDim.x + threadIdx.x) >> 5;
    int lane = threadIdx.x & 31;
    if (gw >= 4 * cpt) return;

    int t = gw / cpt;
    int c = gw - t * cpt;

    const float* emb;
    const int* vals;
    int n;
    switch (t) {
        case 0: emb = e0; vals = v0; n = n0; break;
        case 1: emb = e1; vals = v1; n = n1; break;
        case 2: emb = e2; vals = v2; n = n2; break;
        default: emb = e3; vals = v3; n = n3; break;
    }

    int s = c * CHUNK;
    if (s >= n) return;
    int e = s + CHUNK < n ? s + CHUNK : n;

    const float2* E = reinterpret_cast<const float2*>(emb);

    // Bag of value s: count of offsets[1..B-1] <= s  (searchsorted right).
    int lo = 1, hi = B;
    while (lo < hi) {
        int mid = (lo + hi) >> 1;
        if (__ldg(&offsets[mid]) <= s) lo = mid + 1; else hi = mid;
    }
    int cur  = lo - 1;
    int next = __ldg(&offsets[cur + 1]);   // offsets[B] = n sentinel

    float* obase = out + t * 64 + 2 * lane;

    float2 acc = make_float2(0.f, 0.f);
    bool any = false;

    for (int base = s; base < e; base += PF) {
        int idxv[PF];
        float2 r[PF];
        #pragma unroll
        for (int k = 0; k < PF; ++k)
            if (base + k < e) idxv[k] = __ldg(&vals[base + k]);
        #pragma unroll
        for (int k = 0; k < PF; ++k)
            if (base + k < e) r[k] = __ldg(&E[(size_t)idxv[k] * 32 + lane]);

        #pragma unroll
        for (int k = 0; k < PF; ++k) {
            int i = base + k;
            if (i >= e) break;
            while (i >= next) {           // crossed bag boundary (warp-uniform)
                if (any) {
                    float* p = obase + (size_t)cur * 256;
                    atomicAdd(p,     acc.x);
                    atomicAdd(p + 1, acc.y);
                    acc = make_float2(0.f, 0.f);
                    any = false;
                }
                ++cur;
                next = __ldg(&offsets[cur + 1]);
            }
            acc.x += r[k].x;
            acc.y += r[k].y;
            any = true;
        }
    }
    if (any) {
        float* p = obase + (size_t)cur * 256;
        atomicAdd(p,     acc.x);
        atomicAdd(p + 1, acc.y);
    }
}

// Divide mean-pooled halves (tables 2,3 -> columns 128..255) by bag length.
// Empty bags already hold 0; dividing by max(len,1) keeps them 0.
__global__ __launch_bounds__(NTHREADS)
void ebc_mean_div(const int* __restrict__ offsets,
                  float* __restrict__ out, int B)
{
    int id = blockIdx.x * blockDim.x + threadIdx.x;   // one float4 each
    int total = B * 32;                               // 32 float4 = 128 floats/bag
    if (id >= total) return;
    int b = id >> 5;
    int q = id & 31;
    int len = __ldg(&offsets[b + 1]) - __ldg(&offsets[b]);
    float inv = 1.0f / (float)(len > 0 ? len : 1);
    float4* p = reinterpret_cast<float4*>(out + (size_t)b * 256 + 128) + q;
    float4 v = *p;
    v.x *= inv; v.y *= inv; v.z *= inv; v.w *= inv;
    *p = v;
}

extern "C" void kernel_launch(void* const* d_in, const int* in_sizes, int n_in,
                              void* d_out, int out_size)
{
    // Resolve inputs by element count (robust to metadata ordering):
    //   emb tables: 64,000,000 elems; values: ~204,800; offsets: B+1 (~4097)
    const float* embs[4] = {nullptr, nullptr, nullptr, nullptr};
    const int*   vals[4] = {nullptr, nullptr, nullptr, nullptr};
    int          vn[4]   = {0, 0, 0, 0};
    const int*   offsets = nullptr;
    int ne = 0, nv = 0;
    for (int i = 0; i < n_in; ++i) {
        if (in_sizes[i] > 10000000) {
            if (ne < 4) embs[ne++] = (const float*)d_in[i];
        } else if (in_sizes[i] > 100000) {
            if (nv < 4) { vals[nv] = (const int*)d_in[i]; vn[nv] = in_sizes[i]; ++nv; }
        } else {
            offsets = (const int*)d_in[i];
        }
    }

    int B = out_size / 256;
    int nmax = vn[0];
    for (int i = 1; i < 4; ++i) if (vn[i] > nmax) nmax = vn[i];
    int cpt = (nmax + CHUNK - 1) / CHUNK;

    cudaMemsetAsync(d_out, 0, (size_t)out_size * sizeof(float), 0);

    int warps = 4 * cpt;
    int blocks = (warps * 32 + NTHREADS - 1) / NTHREADS;
    ebc_gather<<<blocks, NTHREADS>>>(
        embs[0], embs[1], embs[2], embs[3],
        vals[0], vals[1], vals[2], vals[3],
        offsets, (float*)d_out, B,
        vn[0], vn[1], vn[2], vn[3], cpt);

    int mthreads = B * 32;
    int mblocks = (mthreads + NTHREADS - 1) / NTHREADS;
    ebc_mean_div<<<mblocks, NTHREADS>>>(offsets, (float*)d_out, B);
}

// round 4
// speedup vs baseline: 1.7823x; 1.0069x over previous
#include <cuda_runtime.h>
#include <cstdint>

// 4-table EmbeddingBagCollection: B bags, D=64, out [B, 4*64] fp32.
// Pooling: tables 0,1 = sum; tables 2,3 = mean (empty bag -> 0).
//
// R4: flat chunked gather, CHUNK=64, double-buffered PF=8 row prefetch
// (16 rows in flight/warp), binary search overlapped with first batch's
// DRAM latency, mean scaling fused into the atomic flush (no second pass).

#define CHUNK 64
#define PF 8
#define NTHREADS 256

__global__ __launch_bounds__(NTHREADS)
void ebc_gather(const float* __restrict__ e0, const float* __restrict__ e1,
                const float* __restrict__ e2, const float* __restrict__ e3,
                const int* __restrict__ v0, const int* __restrict__ v1,
                const int* __restrict__ v2, const int* __restrict__ v3,
                const int* __restrict__ offsets,
                float* __restrict__ out, int B,
                int n0, int n1, int n2, int n3, int cpt)
{
    int gw   = (blockIdx.x * blockDim.x + threadIdx.x) >> 5;
    int lane = threadIdx.x & 31;
    if (gw >= 4 * cpt) return;

    int t = gw / cpt;
    int c = gw - t * cpt;

    const float* emb;
    const int* vals;
    int n;
    switch (t) {
        case 0: emb = e0; vals = v0; n = n0; break;
        case 1: emb = e1; vals = v1; n = n1; break;
        case 2: emb = e2; vals = v2; n = n2; break;
        default: emb = e3; vals = v3; n = n3; break;
    }

    int s = c * CHUNK;
    if (s >= n) return;
    int e = s + CHUNK < n ? s + CHUNK : n;

    const float2* E = reinterpret_cast<const float2*>(emb);
    bool isMean = (t >= 2);

    // ---- prefetch batch 0 into A (issued BEFORE the search so the search
    //      latency hides inside these loads' DRAM latency) ----
    int    idxA[PF]; float2 rA[PF];
    int    idxB[PF]; float2 rB[PF];
    int nA = (e - s) < PF ? (e - s) : PF;
    #pragma unroll
    for (int k = 0; k < PF; ++k)
        if (k < nA) idxA[k] = __ldg(&vals[s + k]);
    #pragma unroll
    for (int k = 0; k < PF; ++k)
        if (k < nA) rA[k] = __ldg(&E[(size_t)idxA[k] * 32 + lane]);

    // ---- binary search: bag of position s ----
    int lo = 1, hi = B;
    while (lo < hi) {
        int mid = (lo + hi) >> 1;
        if (__ldg(&offsets[mid]) <= s) lo = mid + 1; else hi = mid;
    }
    int cur      = lo - 1;
    int bagStart = __ldg(&offsets[cur]);
    int next     = __ldg(&offsets[cur + 1]);

    float* obase = out + t * 64 + 2 * lane;
    float2 acc = make_float2(0.f, 0.f);
    bool any = false;

#define FLUSH()                                                          \
    do {                                                                 \
        float sc = isMean ? 1.0f / (float)(next - bagStart) : 1.0f;      \
        float* p = obase + (size_t)cur * 256;                            \
        atomicAdd(p,     acc.x * sc);                                    \
        atomicAdd(p + 1, acc.y * sc);                                    \
    } while (0)

#define CONSUME(IDXBUF, RBUF, BASE, CNT)                                 \
    do {                                                                 \
        _Pragma("unroll")                                                \
        for (int k = 0; k < PF; ++k) {                                   \
            if (k >= (CNT)) break;                                       \
            int i = (BASE) + k;                                          \
            while (i >= next) {                                          \
                if (any) { FLUSH(); acc = make_float2(0.f, 0.f); any = false; } \
                ++cur;                                                   \
                bagStart = next;                                         \
                next = __ldg(&offsets[cur + 1]);                         \
            }                                                            \
            acc.x += RBUF[k].x;                                          \
            acc.y += RBUF[k].y;                                          \
            any = true;                                                  \
        }                                                                \
    } while (0)

    // ---- pipelined main loop: prefetch B while consuming A, and vice versa ----
    int base = s;
    while (base < e) {
        // prefetch batch base+PF into B
        int bB = base + PF;
        int nB = bB < e ? ((e - bB) < PF ? (e - bB) : PF) : 0;
        #pragma unroll
        for (int k = 0; k < PF; ++k)
            if (k < nB) idxB[k] = __ldg(&vals[bB + k]);
        #pragma unroll
        for (int k = 0; k < PF; ++k)
            if (k < nB) rB[k] = __ldg(&E[(size_t)idxB[k] * 32 + lane]);

        CONSUME(idxA, rA, base, nA);

        base = bB;
        if (base >= e) break;

        // prefetch batch base+PF into A
        int bA = base + PF;
        nA = bA < e ? ((e - bA) < PF ? (e - bA) : PF) : 0;
        #pragma unroll
        for (int k = 0; k < PF; ++k)
            if (k < nA) idxA[k] = __ldg(&vals[bA + k]);
        #pragma unroll
        for (int k = 0; k < PF; ++k)
            if (k < nA) rA[k] = __ldg(&E[(size_t)idxA[k] * 32 + lane]);

        CONSUME(idxB, rB, base, nB);

        base = bA;
    }

    if (any) FLUSH();

#undef CONSUME
#undef FLUSH
}

extern "C" void kernel_launch(void* const* d_in, const int* in_sizes, int n_in,
                              void* d_out, int out_size)
{
    // Resolve inputs by element count (robust to metadata ordering):
    //   emb tables: 64,000,000 elems; values: ~204,800; offsets: B+1 (~4097)
    const float* embs[4] = {nullptr, nullptr, nullptr, nullptr};
    const int*   vals[4] = {nullptr, nullptr, nullptr, nullptr};
    int          vn[4]   = {0, 0, 0, 0};
    const int*   offsets = nullptr;
    int ne = 0, nv = 0;
    for (int i = 0; i < n_in; ++i) {
        if (in_sizes[i] > 10000000) {
            if (ne < 4) embs[ne++] = (const float*)d_in[i];
        } else if (in_sizes[i] > 100000) {
            if (nv < 4) { vals[nv] = (const int*)d_in[i]; vn[nv] = in_sizes[i]; ++nv; }
        } else {
            offsets = (const int*)d_in[i];
        }
    }

    int B = out_size / 256;
    int nmax = vn[0];
    for (int i = 1; i < 4; ++i) if (vn[i] > nmax) nmax = vn[i];
    int cpt = (nmax + CHUNK - 1) / CHUNK;

    cudaMemsetAsync(d_out, 0, (size_t)out_size * sizeof(float), 0);

    int warps = 4 * cpt;
    int blocks = (warps * 32 + NTHREADS - 1) / NTHREADS;
    ebc_gather<<<blocks, NTHREADS>>>(
        embs[0], embs[1], embs[2], embs[3],
        vals[0], vals[1], vals[2], vals[3],
        offsets, (float*)d_out, B,
        vn[0], vn[1], vn[2], vn[3], cpt);
}